// round 12
// baseline (speedup 1.0000x reference)
#include <cuda_runtime.h>
#include <cstdint>

// Problem constants (fixed by reference setup_inputs)
#define B_   4
#define N_   16384
#define C_   64
#define NQ_  256
#define NS_  32

// Output layout (verified passing since R1):
//   grouped_xyz : [B, 3,   NQ, NS]
//   new_features: [B, 3+C, NQ, NS]
//   mask        : [B, NQ, NS]  (all False)
//
// Structure: 256 CTAs, each handles FOUR queries of one batch.
// Single global-memory round: xyz prefix (64 pts), 4 boxes, and each warp's
// 8 feature-channel windows (cols 0..63) are ALL front-batched; the
// data-dependent "gather" is done with register shuffles. No block barrier.

__global__ __launch_bounds__(256) void boxquery_group_kernel(
    const float* __restrict__ xyz,    // [B, N, 3]
    const float* __restrict__ feat,   // [B, C, N]
    const float* __restrict__ qbox,   // [B, NQ, 6]
    float* __restrict__ out)
{
    const int cta  = blockIdx.x;        // 0 .. 255
    const int b    = cta >> 6;          // 64 CTAs per batch
    const int q0   = (cta & 63) << 2;   // queries q0 .. q0+3
    const int tid  = threadIdx.x;
    const int lane = tid & 31;
    const int w    = tid >> 5;
    const unsigned FULL  = 0xffffffffu;
    const unsigned below = (1u << lane) - 1u;

    // Per-warp selected indices, per query (warp-autonomous).
    __shared__ int sidx_sh[8][4][NS_];

    const float*  xb  = xyz + (size_t)b * N_ * 3;
    const float2* xb2 = (const float2*)xb;        // batch base is 16B-aligned

    // ================= FRONT-BATCHED LOADS (single memory round) ==========
    // lane ℓ holds points 2ℓ and 2ℓ+1 (floats 6ℓ..6ℓ+5)
    const float2 a0 = xb2[3 * lane + 0];   // x0, y0
    const float2 a1 = xb2[3 * lane + 1];   // z0, x1
    const float2 a2 = xb2[3 * lane + 2];   // y1, z1

    // 4 boxes = 24 floats, one lane-parallel load + shfl broadcasts later
    const float* qb = qbox + (size_t)(b * NQ_ + q0) * 6;
    const float bxv = (lane < 24) ? qb[lane] : 0.0f;

    // Feature windows: warp w owns channels 8w..8w+7; cols 0..63 per channel
    const float* fb = feat + (size_t)b * C_ * N_ + (size_t)(8 * w) * N_;
    float lo[8], hi[8];
    #pragma unroll
    for (int j = 0; j < 8; ++j) {
        lo[j] = fb[(size_t)j * N_ + lane];        // coalesced 128B
        hi[j] = fb[(size_t)j * N_ + 32 + lane];
    }

    // ================= SELECTION (4 queries, in-warp, ALU only) ============
    // predicate ("sort key == 0"): (n == 0) || !in_box(n)
    int totals[4];
    #pragma unroll
    for (int qi = 0; qi < 4; ++qi) {
        const float cx = __shfl_sync(FULL, bxv, 6 * qi + 0);
        const float cy = __shfl_sync(FULL, bxv, 6 * qi + 1);
        const float cz = __shfl_sync(FULL, bxv, 6 * qi + 2);
        const float hx = 0.5f * __shfl_sync(FULL, bxv, 6 * qi + 3);
        const float hy = 0.5f * __shfl_sync(FULL, bxv, 6 * qi + 4);
        const float hz = 0.5f * __shfl_sync(FULL, bxv, 6 * qi + 5);

        const bool inb0 = (fabsf(a0.x - cx) <= hx) & (fabsf(a0.y - cy) <= hy) &
                          (fabsf(a1.x - cz) <= hz);
        const bool inb1 = (fabsf(a1.y - cx) <= hx) & (fabsf(a2.x - cy) <= hy) &
                          (fabsf(a2.y - cz) <= hz);
        const bool acc0 = (lane == 0) || (!inb0);   // n = 2ℓ
        const bool acc1 = !inb1;                    // n = 2ℓ+1 ≥ 1
        const unsigned m0 = __ballot_sync(FULL, acc0);
        const unsigned m1 = __ballot_sync(FULL, acc1);
        const int excl = __popc(m0 & below) + __popc(m1 & below);
        totals[qi] = __popc(m0) + __popc(m1);
        if (acc0 && excl < NS_)               sidx_sh[w][qi][excl]        = 2 * lane;
        if (acc1 && (excl + (int)acc0) < NS_) sidx_sh[w][qi][excl + acc0] = 2 * lane + 1;
    }

    // ---- Fallback (statistically never taken): exact argsort order over
    // the remaining range. Zero-key over [64,N) asc, then in-box (n>0) asc. --
    #pragma unroll
    for (int qi = 0; qi < 4; ++qi) {
        if (totals[qi] < NS_) {
            const float cx = __shfl_sync(FULL, bxv, 6 * qi + 0);
            const float cy = __shfl_sync(FULL, bxv, 6 * qi + 1);
            const float cz = __shfl_sync(FULL, bxv, 6 * qi + 2);
            const float hx = 0.5f * __shfl_sync(FULL, bxv, 6 * qi + 3);
            const float hy = 0.5f * __shfl_sync(FULL, bxv, 6 * qi + 4);
            const float hz = 0.5f * __shfl_sync(FULL, bxv, 6 * qi + 5);
            int count = totals[qi], base = 64;
            while (count < NS_ && base < N_) {
                const int nn = base + lane;
                const bool inb = (fabsf(xb[nn*3+0] - cx) <= hx) &
                                 (fabsf(xb[nn*3+1] - cy) <= hy) &
                                 (fabsf(xb[nn*3+2] - cz) <= hz);
                const bool acc = !inb;
                const unsigned m   = __ballot_sync(FULL, acc);
                const int      pre = __popc(m & below);
                if (acc && (count + pre) < NS_) sidx_sh[w][qi][count + pre] = nn;
                count += __popc(m);
                base  += 32;
            }
            base = 0;
            while (count < NS_ && base < N_) {
                const int nn = base + lane;
                const bool inb = (fabsf(xb[nn*3+0] - cx) <= hx) &
                                 (fabsf(xb[nn*3+1] - cy) <= hy) &
                                 (fabsf(xb[nn*3+2] - cz) <= hz);
                const bool acc = (nn != 0) && inb;
                const unsigned m   = __ballot_sync(FULL, acc);
                const int      pre = __popc(m & below);
                if (acc && (count + pre) < NS_) sidx_sh[w][qi][count + pre] = nn;
                count += __popc(m);
                base  += 32;
            }
        }
    }
    __syncwarp();
    int n[4];
    #pragma unroll
    for (int qi = 0; qi < 4; ++qi) n[qi] = sidx_sh[w][qi][lane];  // slot = lane

    // ================= OUTPUTS =============================================
    float* out_gx = out;                                        // [B,3,NQ,NS]
    float* out_nf = out + (size_t)B_ * 3 * NQ_ * NS_;           // [B,3+C,NQ,NS]
    float* out_mk = out_nf + (size_t)B_ * (3 + C_) * NQ_ * NS_; // [B,NQ,NS]
    const size_t row_pitch = (size_t)NQ_ * NS_;

    // ---- Warps 0..3: grouped_xyz rows + mask for query q0+w (shfl gather) --
    if (w < 4) {
        const int q  = q0 + w;
        const int nn = n[w];
        const float cx = __shfl_sync(FULL, bxv, 6 * w + 0);
        const float cy = __shfl_sync(FULL, bxv, 6 * w + 1);
        const float cz = __shfl_sync(FULL, bxv, 6 * w + 2);
        const int   src = nn >> 1;
        const bool  odd = nn & 1;
        const float xe = __shfl_sync(FULL, a0.x, src), xo = __shfl_sync(FULL, a1.y, src);
        const float ye = __shfl_sync(FULL, a0.y, src), yo = __shfl_sync(FULL, a2.x, src);
        const float ze = __shfl_sync(FULL, a1.x, src), zo = __shfl_sync(FULL, a2.y, src);
        float gx = (odd ? xo : xe) - cx;
        float gy = (odd ? yo : ye) - cy;
        float gz = (odd ? zo : ze) - cz;
        if (__any_sync(FULL, nn >= 64)) {           // fallback lanes only
            if (nn >= 64) {
                gx = xb[nn * 3 + 0] - cx;
                gy = xb[nn * 3 + 1] - cy;
                gz = xb[nn * 3 + 2] - cz;
            }
        }
        const size_t gx_row = ((size_t)(b * 3 + 0) * NQ_ + q) * NS_ + lane;
        const size_t nf_row = ((size_t)(b * (3 + C_) + 0) * NQ_ + q) * NS_ + lane;
        out_gx[gx_row + 0 * row_pitch] = gx;
        out_gx[gx_row + 1 * row_pitch] = gy;
        out_gx[gx_row + 2 * row_pitch] = gz;
        out_nf[nf_row + 0 * row_pitch] = gx;
        out_nf[nf_row + 1 * row_pitch] = gy;
        out_nf[nf_row + 2 * row_pitch] = gz;
        out_mk[(size_t)(b * NQ_ + q) * NS_ + lane] = 0.0f;
    }

    // ---- Features: warp w -> channels 8w..8w+7, 4 queries, shfl gather ----
    float* nf_base = out_nf + ((size_t)(b * (3 + C_) + 3 + 8 * w) * NQ_ + q0) * NS_ + lane;
    #pragma unroll
    for (int qi = 0; qi < 4; ++qi) {
        const int nq = n[qi];
        float v[8];
        #pragma unroll
        for (int j = 0; j < 8; ++j) {
            const float vl = __shfl_sync(FULL, lo[j], nq);   // src = nq & 31
            const float vh = __shfl_sync(FULL, hi[j], nq);
            v[j] = (nq < 32) ? vl : vh;
        }
        if (__any_sync(FULL, nq >= 64)) {           // fallback lanes only
            if (nq >= 64) {
                #pragma unroll
                for (int j = 0; j < 8; ++j) v[j] = fb[(size_t)j * N_ + nq];
            }
        }
        float* dst = nf_base + (size_t)qi * NS_;
        #pragma unroll
        for (int j = 0; j < 8; ++j)
            dst[(size_t)j * row_pitch] = v[j];      // warp-coalesced STG.32
    }
}

extern "C" void kernel_launch(void* const* d_in, const int* in_sizes, int n_in,
                              void* d_out, int out_size)
{
    const float* key_xyz      = (const float*)d_in[0];  // [4,16384,3]
    const float* key_features = (const float*)d_in[1];  // [4,64,16384]
    const float* query_box    = (const float*)d_in[2];  // [4,256,6]
    float* out = (float*)d_out;

    boxquery_group_kernel<<<(B_ * NQ_) / 4, 256>>>(key_xyz, key_features, query_box, out);
}

// round 13
// speedup vs baseline: 1.0296x; 1.0296x over previous
#include <cuda_runtime.h>
#include <cstdint>

// Problem constants (fixed by reference setup_inputs)
#define B_   4
#define N_   16384
#define C_   64
#define NQ_  256
#define NS_  32

// Output layout (verified passing since R1):
//   grouped_xyz : [B, 3,   NQ, NS]
//   new_features: [B, 3+C, NQ, NS]
//   mask        : [B, NQ, NS]  (all False)
//
// Structure (R9 baseline + smem-staged feature gather):
// 512 CTAs, each handles TWO queries of one batch. Single global-memory
// round: xyz prefix (64 pts), 2 boxes, and each warp's 8 feature-channel
// windows (cols 0..63) are front-batched; the data-dependent gather is done
// from SHARED MEMORY (LDS, 29cy) instead of a second global round (~250cy).
// No block-level barrier anywhere.

__global__ __launch_bounds__(256) void boxquery_group_kernel(
    const float* __restrict__ xyz,    // [B, N, 3]
    const float* __restrict__ feat,   // [B, C, N]
    const float* __restrict__ qbox,   // [B, NQ, 6]
    float* __restrict__ out)
{
    const int cta  = blockIdx.x;        // 0 .. 511
    const int b    = cta >> 7;          // 128 CTAs per batch
    const int q0   = (cta & 127) << 1;  // queries q0, q0+1
    const int tid  = threadIdx.x;
    const int lane = tid & 31;
    const int w    = tid >> 5;
    const unsigned FULL  = 0xffffffffu;
    const unsigned below = (1u << lane) - 1u;

    // Per-warp state (warp-autonomous; no __syncthreads in this kernel).
    __shared__ int   sidx_sh[8][2][NS_];
    __shared__ float sfeat[8][8][64];   // [warp][channel][col 0..63]

    const float*  xb  = xyz + (size_t)b * N_ * 3;
    const float2* xb2 = (const float2*)xb;       // batch base is 16B-aligned

    // ================= FRONT-BATCHED LOADS (single global round) ==========
    // lane ℓ holds points 2ℓ and 2ℓ+1 (floats 6ℓ..6ℓ+5)
    const float2 a0 = xb2[3 * lane + 0];   // x0, y0
    const float2 a1 = xb2[3 * lane + 1];   // z0, x1
    const float2 a2 = xb2[3 * lane + 2];   // y1, z1

    // 2 boxes (12 floats) as 6 uniform float2 loads
    const float2* boxA = (const float2*)(qbox + (size_t)(b * NQ_ + q0) * 6);
    const float2 A01 = boxA[0], A23 = boxA[1], A45 = boxA[2];
    const float2 B01 = boxA[3], B23 = boxA[4], B45 = boxA[5];

    // Feature windows: warp w owns channels 8w..8w+7; lane loads cols 2ℓ,2ℓ+1
    const float* fb = feat + (size_t)b * C_ * N_ + (size_t)(8 * w) * N_;
    float2 fw[8];
    #pragma unroll
    for (int j = 0; j < 8; ++j)
        fw[j] = ((const float2*)(fb + (size_t)j * N_))[lane];   // coalesced 256B

    const float cxA = A01.x, cyA = A01.y, czA = A23.x;
    const float hxA = 0.5f * A23.y, hyA = 0.5f * A45.x, hzA = 0.5f * A45.y;
    const float cxB = B01.x, cyB = B01.y, czB = B23.x;
    const float hxB = 0.5f * B23.y, hyB = 0.5f * B45.x, hzB = 0.5f * B45.y;

    // ================= SELECTION (2 queries, in-warp, ALU only) ============
    // predicate ("sort key == 0"): (n == 0) || !in_box(n)
    int totals[2];
    {
        const bool inb0 = (fabsf(a0.x - cxA) <= hxA) & (fabsf(a0.y - cyA) <= hyA) &
                          (fabsf(a1.x - czA) <= hzA);
        const bool inb1 = (fabsf(a1.y - cxA) <= hxA) & (fabsf(a2.x - cyA) <= hyA) &
                          (fabsf(a2.y - czA) <= hzA);
        const bool acc0 = (lane == 0) || (!inb0);
        const bool acc1 = !inb1;
        const unsigned m0 = __ballot_sync(FULL, acc0);
        const unsigned m1 = __ballot_sync(FULL, acc1);
        const int excl = __popc(m0 & below) + __popc(m1 & below);
        totals[0] = __popc(m0) + __popc(m1);
        if (acc0 && excl < NS_)               sidx_sh[w][0][excl]        = 2 * lane;
        if (acc1 && (excl + (int)acc0) < NS_) sidx_sh[w][0][excl + acc0] = 2 * lane + 1;
    }
    {
        const bool inb0 = (fabsf(a0.x - cxB) <= hxB) & (fabsf(a0.y - cyB) <= hyB) &
                          (fabsf(a1.x - czB) <= hzB);
        const bool inb1 = (fabsf(a1.y - cxB) <= hxB) & (fabsf(a2.x - cyB) <= hyB) &
                          (fabsf(a2.y - czB) <= hzB);
        const bool acc0 = (lane == 0) || (!inb0);
        const bool acc1 = !inb1;
        const unsigned m0 = __ballot_sync(FULL, acc0);
        const unsigned m1 = __ballot_sync(FULL, acc1);
        const int excl = __popc(m0 & below) + __popc(m1 & below);
        totals[1] = __popc(m0) + __popc(m1);
        if (acc0 && excl < NS_)               sidx_sh[w][1][excl]        = 2 * lane;
        if (acc1 && (excl + (int)acc0) < NS_) sidx_sh[w][1][excl + acc0] = 2 * lane + 1;
    }

    // ---- Stage feature windows to shared (waits only on the feat loads) ----
    #pragma unroll
    for (int j = 0; j < 8; ++j)
        ((float2*)&sfeat[w][j][0])[lane] = fw[j];   // STS.64

    // ---- Fallback (statistically never taken): exact argsort order over
    // the remaining range. Zero-key over [64,N) asc, then in-box (n>0) asc. --
    #pragma unroll
    for (int j = 0; j < 2; ++j) {
        if (totals[j] < NS_) {
            const float cx = j ? cxB : cxA, cy = j ? cyB : cyA, cz = j ? czB : czA;
            const float hx = j ? hxB : hxA, hy = j ? hyB : hyA, hz = j ? hzB : hzA;
            int count = totals[j], base = 64;
            while (count < NS_ && base < N_) {
                const int nn = base + lane;
                const bool inb = (fabsf(xb[nn*3+0] - cx) <= hx) &
                                 (fabsf(xb[nn*3+1] - cy) <= hy) &
                                 (fabsf(xb[nn*3+2] - cz) <= hz);
                const bool acc = !inb;   // nn > 0 guaranteed
                const unsigned m   = __ballot_sync(FULL, acc);
                const int      pre = __popc(m & below);
                if (acc && (count + pre) < NS_) sidx_sh[w][j][count + pre] = nn;
                count += __popc(m);
                base  += 32;
            }
            base = 0;
            while (count < NS_ && base < N_) {
                const int nn = base + lane;
                const bool inb = (fabsf(xb[nn*3+0] - cx) <= hx) &
                                 (fabsf(xb[nn*3+1] - cy) <= hy) &
                                 (fabsf(xb[nn*3+2] - cz) <= hz);
                const bool acc = (nn != 0) && inb;
                const unsigned m   = __ballot_sync(FULL, acc);
                const int      pre = __popc(m & below);
                if (acc && (count + pre) < NS_) sidx_sh[w][j][count + pre] = nn;
                count += __popc(m);
                base  += 32;
            }
        }
    }
    __syncwarp();
    const int n0 = sidx_sh[w][0][lane];   // slot k = lane, query q0
    const int n1 = sidx_sh[w][1][lane];   // slot k = lane, query q0+1

    // ================= OUTPUTS =============================================
    float* out_gx = out;                                        // [B,3,NQ,NS]
    float* out_nf = out + (size_t)B_ * 3 * NQ_ * NS_;           // [B,3+C,NQ,NS]
    float* out_mk = out_nf + (size_t)B_ * (3 + C_) * NQ_ * NS_; // [B,NQ,NS]
    const size_t row_pitch = (size_t)NQ_ * NS_;

    // ---- Warps 0 and 1: grouped_xyz rows (both tensors) + mask ----
    if (w < 2) {
        const int q = q0 + w;
        const int n = w ? n1 : n0;
        const float cx = w ? cxB : cxA, cy = w ? cyB : cyA, cz = w ? czB : czA;
        const float gx = xb[n * 3 + 0] - cx;   // ~2 cache lines, L1-resident
        const float gy = xb[n * 3 + 1] - cy;
        const float gz = xb[n * 3 + 2] - cz;
        const size_t gx_row = ((size_t)(b * 3 + 0) * NQ_ + q) * NS_ + lane;
        const size_t nf_row = ((size_t)(b * (3 + C_) + 0) * NQ_ + q) * NS_ + lane;
        out_gx[gx_row + 0 * row_pitch] = gx;
        out_gx[gx_row + 1 * row_pitch] = gy;
        out_gx[gx_row + 2 * row_pitch] = gz;
        out_nf[nf_row + 0 * row_pitch] = gx;
        out_nf[nf_row + 1 * row_pitch] = gy;
        out_nf[nf_row + 2 * row_pitch] = gz;
        out_mk[(size_t)(b * NQ_ + q) * NS_ + lane] = 0.0f;
    }

    // ---- Features: warp w -> channels 8w..8w+7, both queries, LDS gather ----
    const int i0 = (n0 < 64) ? n0 : 63;     // clamp (fallback lanes overwritten)
    const int i1 = (n1 < 64) ? n1 : 63;
    float v0[8], v1[8];
    #pragma unroll
    for (int j = 0; j < 8; ++j) {
        v0[j] = sfeat[w][j][i0];            // LDS.32, ~distinct banks (n asc)
        v1[j] = sfeat[w][j][i1];
    }
    if (__any_sync(FULL, (n0 >= 64) | (n1 >= 64))) {    // never taken in practice
        if (n0 >= 64) {
            #pragma unroll
            for (int j = 0; j < 8; ++j) v0[j] = fb[(size_t)j * N_ + n0];
        }
        if (n1 >= 64) {
            #pragma unroll
            for (int j = 0; j < 8; ++j) v1[j] = fb[(size_t)j * N_ + n1];
        }
    }

    float* nfA = out_nf + ((size_t)(b * (3 + C_) + 3 + 8 * w) * NQ_ + q0)     * NS_ + lane;
    float* nfB = out_nf + ((size_t)(b * (3 + C_) + 3 + 8 * w) * NQ_ + q0 + 1) * NS_ + lane;
    #pragma unroll
    for (int j = 0; j < 8; ++j) {
        nfA[(size_t)j * row_pitch] = v0[j];     // warp-coalesced STG.32
        nfB[(size_t)j * row_pitch] = v1[j];
    }
}

extern "C" void kernel_launch(void* const* d_in, const int* in_sizes, int n_in,
                              void* d_out, int out_size)
{
    const float* key_xyz      = (const float*)d_in[0];  // [4,16384,3]
    const float* key_features = (const float*)d_in[1];  // [4,64,16384]
    const float* query_box    = (const float*)d_in[2];  // [4,256,6]
    float* out = (float*)d_out;

    boxquery_group_kernel<<<(B_ * NQ_) / 2, 256>>>(key_xyz, key_features, query_box, out);
}

// round 14
// speedup vs baseline: 1.2193x; 1.1842x over previous
#include <cuda_runtime.h>
#include <cstdint>

// Problem constants (fixed by reference setup_inputs)
#define B_   4
#define N_   16384
#define C_   64
#define NQ_  256
#define NS_  32

// Output layout (verified passing since R1):
//   grouped_xyz : [B, 3,   NQ, NS]
//   new_features: [B, 3+C, NQ, NS]
//   mask        : [B, NQ, NS]  (all False; index 0 can only land in slot 0,
//                               which the reference forces to False)
//
// Structure: R9 (best known: 512 CTAs, 2 queries/CTA, warp-autonomous, no
// block barrier) + L1-warming prefetch of each warp's feature-gather window
// (cols 0..63 of channels 8w..8w+7) issued with the front-batched loads, so
// the later data-dependent gathers hit L1 (~39cy) instead of L2 (~250cy).

__global__ __launch_bounds__(256) void boxquery_group_kernel(
    const float* __restrict__ xyz,    // [B, N, 3]
    const float* __restrict__ feat,   // [B, C, N]
    const float* __restrict__ qbox,   // [B, NQ, 6]
    float* __restrict__ out)
{
    const int cta  = blockIdx.x;        // 0 .. 511
    const int b    = cta >> 7;          // 128 CTAs per batch
    const int q0   = (cta & 127) << 1;  // queries q0, q0+1
    const int tid  = threadIdx.x;
    const int lane = tid & 31;
    const int w    = tid >> 5;
    const unsigned FULL  = 0xffffffffu;
    const unsigned below = (1u << lane) - 1u;

    // Per-warp selected indices (warp-autonomous; NO block barrier).
    __shared__ int sidx_sh[8][2][NS_];

    const float*  xb  = xyz + (size_t)b * N_ * 3;
    const float2* xb2 = (const float2*)xb;       // batch base is 16B-aligned

    // ================= FRONT-BATCHED INDEPENDENT LOADS =====================
    // lane ℓ holds points 2ℓ and 2ℓ+1 (floats 6ℓ..6ℓ+5)
    const float2 a0 = xb2[3 * lane + 0];   // x0, y0
    const float2 a1 = xb2[3 * lane + 1];   // z0, x1
    const float2 a2 = xb2[3 * lane + 2];   // y1, z1

    // 2 boxes (12 floats) as 6 uniform float2 loads
    const float2* boxA = (const float2*)(qbox + (size_t)(b * NQ_ + q0) * 6);
    const float2 A01 = boxA[0], A23 = boxA[1], A45 = boxA[2];
    const float2 B01 = boxA[3], B23 = boxA[4], B45 = boxA[5];

    // L1 warming: touch cols 2ℓ,2ℓ+1 of channels 8w..8w+7 (results unused;
    // asm volatile keeps the loads). Covers the full gather window 0..63.
    const float* fb = feat + (size_t)b * C_ * N_ + (size_t)(8 * w) * N_;
    {
        const float2* fwp = (const float2*)fb + lane;
        #pragma unroll
        for (int j = 0; j < 8; ++j) {
            float wx, wy;
            asm volatile("ld.global.nc.v2.f32 {%0,%1}, [%2];"
                         : "=f"(wx), "=f"(wy)
                         : "l"(fwp + (size_t)j * (N_ / 2)));
        }
    }

    const float cxA = A01.x, cyA = A01.y, czA = A23.x;
    const float hxA = 0.5f * A23.y, hyA = 0.5f * A45.x, hzA = 0.5f * A45.y;
    const float cxB = B01.x, cyB = B01.y, czB = B23.x;
    const float hxB = 0.5f * B23.y, hyB = 0.5f * B45.x, hzB = 0.5f * B45.y;

    // ================= SELECTION (2 queries, in-warp, ALU only) ============
    // predicate ("sort key == 0"): (n == 0) || !in_box(n)
    int totals[2];
    {
        const bool inb0 = (fabsf(a0.x - cxA) <= hxA) & (fabsf(a0.y - cyA) <= hyA) &
                          (fabsf(a1.x - czA) <= hzA);
        const bool inb1 = (fabsf(a1.y - cxA) <= hxA) & (fabsf(a2.x - cyA) <= hyA) &
                          (fabsf(a2.y - czA) <= hzA);
        const bool acc0 = (lane == 0) || (!inb0);   // n = 2ℓ
        const bool acc1 = !inb1;                    // n = 2ℓ+1 ≥ 1
        const unsigned m0 = __ballot_sync(FULL, acc0);
        const unsigned m1 = __ballot_sync(FULL, acc1);
        const int excl = __popc(m0 & below) + __popc(m1 & below);
        totals[0] = __popc(m0) + __popc(m1);
        if (acc0 && excl < NS_)               sidx_sh[w][0][excl]        = 2 * lane;
        if (acc1 && (excl + (int)acc0) < NS_) sidx_sh[w][0][excl + acc0] = 2 * lane + 1;
    }
    {
        const bool inb0 = (fabsf(a0.x - cxB) <= hxB) & (fabsf(a0.y - cyB) <= hyB) &
                          (fabsf(a1.x - czB) <= hzB);
        const bool inb1 = (fabsf(a1.y - cxB) <= hxB) & (fabsf(a2.x - cyB) <= hyB) &
                          (fabsf(a2.y - czB) <= hzB);
        const bool acc0 = (lane == 0) || (!inb0);
        const bool acc1 = !inb1;
        const unsigned m0 = __ballot_sync(FULL, acc0);
        const unsigned m1 = __ballot_sync(FULL, acc1);
        const int excl = __popc(m0 & below) + __popc(m1 & below);
        totals[1] = __popc(m0) + __popc(m1);
        if (acc0 && excl < NS_)               sidx_sh[w][1][excl]        = 2 * lane;
        if (acc1 && (excl + (int)acc0) < NS_) sidx_sh[w][1][excl + acc0] = 2 * lane + 1;
    }

    // ---- Fallback (statistically never taken): exact argsort order.
    // Continue zero-key scan over [64, N), then in-box (n>0) ascending. ----
    #pragma unroll
    for (int j = 0; j < 2; ++j) {
        if (totals[j] < NS_) {
            const float cx = j ? cxB : cxA, cy = j ? cyB : cyA, cz = j ? czB : czA;
            const float hx = j ? hxB : hxA, hy = j ? hyB : hyA, hz = j ? hzB : hzA;
            int count = totals[j], base = 64;
            while (count < NS_ && base < N_) {
                const int nn = base + lane;
                const bool inb = (fabsf(xb[nn*3+0] - cx) <= hx) &
                                 (fabsf(xb[nn*3+1] - cy) <= hy) &
                                 (fabsf(xb[nn*3+2] - cz) <= hz);
                const bool acc = !inb;   // nn > 0 guaranteed
                const unsigned m   = __ballot_sync(FULL, acc);
                const int      pre = __popc(m & below);
                if (acc && (count + pre) < NS_) sidx_sh[w][j][count + pre] = nn;
                count += __popc(m);
                base  += 32;
            }
            base = 0;
            while (count < NS_ && base < N_) {
                const int nn = base + lane;
                const bool inb = (fabsf(xb[nn*3+0] - cx) <= hx) &
                                 (fabsf(xb[nn*3+1] - cy) <= hy) &
                                 (fabsf(xb[nn*3+2] - cz) <= hz);
                const bool acc = (nn != 0) && inb;
                const unsigned m   = __ballot_sync(FULL, acc);
                const int      pre = __popc(m & below);
                if (acc && (count + pre) < NS_) sidx_sh[w][j][count + pre] = nn;
                count += __popc(m);
                base  += 32;
            }
        }
    }
    __syncwarp();
    const int n0 = sidx_sh[w][0][lane];   // slot k = lane, query q0
    const int n1 = sidx_sh[w][1][lane];   // slot k = lane, query q0+1

    // ================= OUTPUTS =============================================
    float* out_gx = out;                                        // [B,3,NQ,NS]
    float* out_nf = out + (size_t)B_ * 3 * NQ_ * NS_;           // [B,3+C,NQ,NS]
    float* out_mk = out_nf + (size_t)B_ * (3 + C_) * NQ_ * NS_; // [B,NQ,NS]
    const size_t row_pitch = (size_t)NQ_ * NS_;

    // ---- Warps 0 and 1: grouped_xyz rows (both tensors) + mask ----
    if (w < 2) {
        const int q = q0 + w;
        const int n = w ? n1 : n0;
        const float cx = w ? cxB : cxA, cy = w ? cyB : cyA, cz = w ? czB : czA;
        const float gx = xb[n * 3 + 0] - cx;   // L1-resident (front loads)
        const float gy = xb[n * 3 + 1] - cy;
        const float gz = xb[n * 3 + 2] - cz;
        const size_t gx_row = ((size_t)(b * 3 + 0) * NQ_ + q) * NS_ + lane;
        const size_t nf_row = ((size_t)(b * (3 + C_) + 0) * NQ_ + q) * NS_ + lane;
        out_gx[gx_row + 0 * row_pitch] = gx;
        out_gx[gx_row + 1 * row_pitch] = gy;
        out_gx[gx_row + 2 * row_pitch] = gz;
        out_nf[nf_row + 0 * row_pitch] = gx;
        out_nf[nf_row + 1 * row_pitch] = gy;
        out_nf[nf_row + 2 * row_pitch] = gz;
        out_mk[(size_t)(b * NQ_ + q) * NS_ + lane] = 0.0f;
    }

    // ---- Features: warp w -> channels 8w..8w+7, both queries interleaved.
    // Gathers now hit L1 thanks to the warming loads. ----
    float* nfA = out_nf + ((size_t)(b * (3 + C_) + 3 + 8 * w) * NQ_ + q0)     * NS_ + lane;
    float* nfB = out_nf + ((size_t)(b * (3 + C_) + 3 + 8 * w) * NQ_ + q0 + 1) * NS_ + lane;

    float v0[8], v1[8];
    #pragma unroll
    for (int j = 0; j < 8; ++j) {
        v0[j] = fb[(size_t)j * N_ + n0];     // 16 independent L1-hit gathers
        v1[j] = fb[(size_t)j * N_ + n1];
    }
    #pragma unroll
    for (int j = 0; j < 8; ++j) {
        nfA[(size_t)j * row_pitch] = v0[j];  // warp-coalesced STG.32
        nfB[(size_t)j * row_pitch] = v1[j];
    }
}

extern "C" void kernel_launch(void* const* d_in, const int* in_sizes, int n_in,
                              void* d_out, int out_size)
{
    const float* key_xyz      = (const float*)d_in[0];  // [4,16384,3]
    const float* key_features = (const float*)d_in[1];  // [4,64,16384]
    const float* query_box    = (const float*)d_in[2];  // [4,256,6]
    float* out = (float*)d_out;

    boxquery_group_kernel<<<(B_ * NQ_) / 2, 256>>>(key_xyz, key_features, query_box, out);
}

// round 15
// speedup vs baseline: 1.2811x; 1.0507x over previous
#include <cuda_runtime.h>
#include <cstdint>

// Problem constants (fixed by reference setup_inputs)
#define B_   4
#define N_   16384
#define C_   64
#define NQ_  256
#define NS_  32

// Output layout (verified passing since R1):
//   grouped_xyz : [B, 3,   NQ, NS]
//   new_features: [B, 3+C, NQ, NS]
//   mask        : [B, NQ, NS]  (all False; index 0 can only land in slot 0,
//                               which the reference forces to False)
//
// Structure: R9 (empirical best: 512 CTAs, 2 queries/CTA, warp-autonomous,
// no block barrier), with all gather/store address arithmetic hoisted above
// the data-dependent point so the post-selection SASS is just IMAD+LDG.

__global__ __launch_bounds__(256) void boxquery_group_kernel(
    const float* __restrict__ xyz,    // [B, N, 3]
    const float* __restrict__ feat,   // [B, C, N]
    const float* __restrict__ qbox,   // [B, NQ, 6]
    float* __restrict__ out)
{
    const int cta  = blockIdx.x;        // 0 .. 511
    const int b    = cta >> 7;          // 128 CTAs per batch
    const int q0   = (cta & 127) << 1;  // queries q0, q0+1
    const int tid  = threadIdx.x;
    const int lane = tid & 31;
    const int w    = tid >> 5;
    const unsigned FULL  = 0xffffffffu;
    const unsigned below = (1u << lane) - 1u;

    // Per-warp selected indices (warp-autonomous; NO block barrier).
    __shared__ int sidx_sh[8][2][NS_];

    const float*  xb  = xyz + (size_t)b * N_ * 3;
    const float2* xb2 = (const float2*)xb;       // batch base is 16B-aligned

    // ================= FRONT-BATCHED INDEPENDENT LOADS =====================
    // lane ℓ holds points 2ℓ and 2ℓ+1 (floats 6ℓ..6ℓ+5)
    const float2 a0 = xb2[3 * lane + 0];   // x0, y0
    const float2 a1 = xb2[3 * lane + 1];   // z0, x1
    const float2 a2 = xb2[3 * lane + 2];   // y1, z1

    // 2 boxes (12 floats) as 6 uniform float2 loads
    const float2* boxA = (const float2*)(qbox + (size_t)(b * NQ_ + q0) * 6);
    const float2 A01 = boxA[0], A23 = boxA[1], A45 = boxA[2];
    const float2 B01 = boxA[3], B23 = boxA[4], B45 = boxA[5];

    const float cxA = A01.x, cyA = A01.y, czA = A23.x;
    const float hxA = 0.5f * A23.y, hyA = 0.5f * A45.x, hzA = 0.5f * A45.y;
    const float cxB = B01.x, cyB = B01.y, czB = B23.x;
    const float hxB = 0.5f * B23.y, hyB = 0.5f * B45.x, hzB = 0.5f * B45.y;

    // Hoisted (index-independent) gather bases: channel rows 8w..8w+7.
    const float* fb = feat + (size_t)b * C_ * N_ + (size_t)(8 * w) * N_;
    const float* fch[8];
    #pragma unroll
    for (int j = 0; j < 8; ++j) fch[j] = fb + (size_t)j * N_;

    // ================= SELECTION (2 queries, in-warp, ALU only) ============
    // predicate ("sort key == 0"): (n == 0) || !in_box(n)
    int totals[2];
    {
        const bool inb0 = (fabsf(a0.x - cxA) <= hxA) & (fabsf(a0.y - cyA) <= hyA) &
                          (fabsf(a1.x - czA) <= hzA);
        const bool inb1 = (fabsf(a1.y - cxA) <= hxA) & (fabsf(a2.x - cyA) <= hyA) &
                          (fabsf(a2.y - czA) <= hzA);
        const bool acc0 = (lane == 0) || (!inb0);   // n = 2ℓ
        const bool acc1 = !inb1;                    // n = 2ℓ+1 ≥ 1
        const unsigned m0 = __ballot_sync(FULL, acc0);
        const unsigned m1 = __ballot_sync(FULL, acc1);
        const int excl = __popc(m0 & below) + __popc(m1 & below);
        totals[0] = __popc(m0) + __popc(m1);
        if (acc0 && excl < NS_)               sidx_sh[w][0][excl]        = 2 * lane;
        if (acc1 && (excl + (int)acc0) < NS_) sidx_sh[w][0][excl + acc0] = 2 * lane + 1;
    }
    {
        const bool inb0 = (fabsf(a0.x - cxB) <= hxB) & (fabsf(a0.y - cyB) <= hyB) &
                          (fabsf(a1.x - czB) <= hzB);
        const bool inb1 = (fabsf(a1.y - cxB) <= hxB) & (fabsf(a2.x - cyB) <= hyB) &
                          (fabsf(a2.y - czB) <= hzB);
        const bool acc0 = (lane == 0) || (!inb0);
        const bool acc1 = !inb1;
        const unsigned m0 = __ballot_sync(FULL, acc0);
        const unsigned m1 = __ballot_sync(FULL, acc1);
        const int excl = __popc(m0 & below) + __popc(m1 & below);
        totals[1] = __popc(m0) + __popc(m1);
        if (acc0 && excl < NS_)               sidx_sh[w][1][excl]        = 2 * lane;
        if (acc1 && (excl + (int)acc0) < NS_) sidx_sh[w][1][excl + acc0] = 2 * lane + 1;
    }

    // ---- Fallback (statistically never taken): exact argsort order.
    // Continue zero-key scan over [64, N), then in-box (n>0) ascending. ----
    #pragma unroll
    for (int j = 0; j < 2; ++j) {
        if (totals[j] < NS_) {
            const float cx = j ? cxB : cxA, cy = j ? cyB : cyA, cz = j ? czB : czA;
            const float hx = j ? hxB : hxA, hy = j ? hyB : hyA, hz = j ? hzB : hzA;
            int count = totals[j], base = 64;
            while (count < NS_ && base < N_) {
                const int nn = base + lane;
                const bool inb = (fabsf(xb[nn*3+0] - cx) <= hx) &
                                 (fabsf(xb[nn*3+1] - cy) <= hy) &
                                 (fabsf(xb[nn*3+2] - cz) <= hz);
                const bool acc = !inb;   // nn > 0 guaranteed
                const unsigned m   = __ballot_sync(FULL, acc);
                const int      pre = __popc(m & below);
                if (acc && (count + pre) < NS_) sidx_sh[w][j][count + pre] = nn;
                count += __popc(m);
                base  += 32;
            }
            base = 0;
            while (count < NS_ && base < N_) {
                const int nn = base + lane;
                const bool inb = (fabsf(xb[nn*3+0] - cx) <= hx) &
                                 (fabsf(xb[nn*3+1] - cy) <= hy) &
                                 (fabsf(xb[nn*3+2] - cz) <= hz);
                const bool acc = (nn != 0) && inb;
                const unsigned m   = __ballot_sync(FULL, acc);
                const int      pre = __popc(m & below);
                if (acc && (count + pre) < NS_) sidx_sh[w][j][count + pre] = nn;
                count += __popc(m);
                base  += 32;
            }
        }
    }

    // Hoisted output pointers (index-independent).
    float* out_gx = out;                                        // [B,3,NQ,NS]
    float* out_nf = out + (size_t)B_ * 3 * NQ_ * NS_;           // [B,3+C,NQ,NS]
    float* out_mk = out_nf + (size_t)B_ * (3 + C_) * NQ_ * NS_; // [B,NQ,NS]
    const size_t row_pitch = (size_t)NQ_ * NS_;
    float* nfA = out_nf + ((size_t)(b * (3 + C_) + 3 + 8 * w) * NQ_ + q0)     * NS_ + lane;
    float* nfB = nfA + NS_;                                     // q0+1 row

    __syncwarp();
    const int n0 = sidx_sh[w][0][lane];   // slot k = lane, query q0
    const int n1 = sidx_sh[w][1][lane];   // slot k = lane, query q0+1

    // ---- Features: 16 independent gathers issued immediately after n0/n1 ----
    float v0[8], v1[8];
    #pragma unroll
    for (int j = 0; j < 8; ++j) {
        v0[j] = fch[j][n0];
        v1[j] = fch[j][n1];
    }

    // ---- Warps 0 and 1: grouped_xyz rows (both tensors) + mask ----
    if (w < 2) {
        const int q = q0 + w;
        const int n = w ? n1 : n0;
        const float cx = w ? cxB : cxA, cy = w ? cyB : cyA, cz = w ? czB : czA;
        const float gx = xb[n * 3 + 0] - cx;   // L1-resident (front loads)
        const float gy = xb[n * 3 + 1] - cy;
        const float gz = xb[n * 3 + 2] - cz;
        const size_t gx_row = ((size_t)(b * 3 + 0) * NQ_ + q) * NS_ + lane;
        const size_t nf_row = ((size_t)(b * (3 + C_) + 0) * NQ_ + q) * NS_ + lane;
        out_gx[gx_row + 0 * row_pitch] = gx;
        out_gx[gx_row + 1 * row_pitch] = gy;
        out_gx[gx_row + 2 * row_pitch] = gz;
        out_nf[nf_row + 0 * row_pitch] = gx;
        out_nf[nf_row + 1 * row_pitch] = gy;
        out_nf[nf_row + 2 * row_pitch] = gz;
        out_mk[(size_t)(b * NQ_ + q) * NS_ + lane] = 0.0f;
    }

    #pragma unroll
    for (int j = 0; j < 8; ++j) {
        nfA[(size_t)j * row_pitch] = v0[j];  // warp-coalesced STG.32
        nfB[(size_t)j * row_pitch] = v1[j];
    }
}

extern "C" void kernel_launch(void* const* d_in, const int* in_sizes, int n_in,
                              void* d_out, int out_size)
{
    const float* key_xyz      = (const float*)d_in[0];  // [4,16384,3]
    const float* key_features = (const float*)d_in[1];  // [4,64,16384]
    const float* query_box    = (const float*)d_in[2];  // [4,256,6]
    float* out = (float*)d_out;

    boxquery_group_kernel<<<(B_ * NQ_) / 2, 256>>>(key_xyz, key_features, query_box, out);
}